// round 3
// baseline (speedup 1.0000x reference)
#include <cuda_runtime.h>

// Neural 2D min-sum LDPC decoder, (3,6)-regular layered graph.
// One CTA per codeword; entire edge state (E = 3*8192 floats = 96KB) lives in
// shared memory for all T iterations. msg[l*N + v] holds v2c after the
// variable phase and c2v after the check phase (in-place, slots uniquely owned:
// per layer each variable appears in exactly one check).
// Check c, layer l owns edges e = l*NV + 2c + {0,1}  (edge_c = i>>1 by construction).

#define NV 8192           // variable nodes
#define MC 4096           // check nodes
#define NL 3              // layers (dv)
#define TPB 1024
#define VPT (NV / TPB)    // 8 variables per thread
#define CPT (MC / TPB)    // 4 checks per thread
#define SMEM_BYTES (NL * NV * 4)   // 96KB message state

__global__ __launch_bounds__(TPB, 1)
void bp_kernel(const float* __restrict__ llr,
               const int*   __restrict__ edge_v,
               const float* __restrict__ beta,
               const float* __restrict__ alpha,
               float* __restrict__ out_f,
               int*   __restrict__ out_i,
               int B, int T, int mode)
{
    extern __shared__ float msg[];   // [NL*NV]

    const int tid = threadIdx.x;

    // Register-resident check->var table (graph fixed across codewords/iters).
    // Thread owns checks c = tid + k*TPB; pk[k][l] packs the layer-l var pair.
    unsigned pk[CPT][NL];
#pragma unroll
    for (int k = 0; k < CPT; k++) {
        int c = tid + k * TPB;
#pragma unroll
        for (int l = 0; l < NL; l++) {
            unsigned v0 = (unsigned)edge_v[l * NV + 2 * c];
            unsigned v1 = (unsigned)edge_v[l * NV + 2 * c + 1];
            pk[k][l] = v0 | (v1 << 16);
        }
    }

    for (int cw = blockIdx.x; cw < B; cw += gridDim.x) {
        // Channel LLRs for this codeword: thread owns v = tid + k*TPB (coalesced).
        float llrv[VPT];
#pragma unroll
        for (int k = 0; k < VPT; k++)
            llrv[k] = llr[(size_t)cw * NV + tid + k * TPB];

        // v2c init = llr at each edge.
#pragma unroll
        for (int l = 0; l < NL; l++)
#pragma unroll
            for (int k = 0; k < VPT; k++)
                msg[l * NV + tid + k * TPB] = llrv[k];
        __syncthreads();

        for (int t = 0; t < T; t++) {
            float bt = __ldg(beta + t);
            float at = __ldg(alpha + t);

            // ---------- check phase: v2c -> c2v (in place) ----------
#pragma unroll 1
            for (int k = 0; k < CPT; k++) {
                int vi[6];
#pragma unroll
                for (int l = 0; l < NL; l++) {
                    vi[2 * l]     = (int)(pk[k][l] & 0xFFFFu);
                    vi[2 * l + 1] = (int)(pk[k][l] >> 16);
                }
                float m[6];
#pragma unroll
                for (int p = 0; p < 6; p++)
                    m[p] = msg[(p >> 1) * NV + vi[p]];   // random smem gather

                // Two-min scan in global edge order (p ascending) reproduces the
                // reference first-occurrence argmin + min2 semantics exactly.
                float min1 = __int_as_float(0x7f800000);
                float min2 = min1;
                int   arg  = 0;
                float prod = 1.0f;
                float s[6];
#pragma unroll
                for (int p = 0; p < 6; p++) {
                    float a  = fabsf(m[p]);
                    float sg = (m[p] > 0.0f) ? 1.0f : ((m[p] < 0.0f) ? -1.0f : 0.0f);
                    s[p] = sg;
                    prod *= sg;                     // sprod, incl. sign(0)=0 case
                    if (a < min1) { min2 = min1; min1 = a; arg = p; }
                    else if (a < min2) { min2 = a; }
                }
                float b1 = bt * prod * min1;
                float b2 = bt * prod * min2;
#pragma unroll
                for (int p = 0; p < 6; p++)
                    msg[(p >> 1) * NV + vi[p]] = ((p == arg) ? b2 : b1) * s[p];
            }
            __syncthreads();

            // ---------- variable phase: c2v -> v2c (skip after last iter) ----------
            if (t + 1 < T) {
#pragma unroll
                for (int k = 0; k < VPT; k++) {
                    int v = tid + k * TPB;
                    float c0 = msg[v];
                    float c1 = msg[NV + v];
                    float c2 = msg[2 * NV + v];
                    float sv = c0 + c1 + c2;
                    float base = llrv[k];
                    msg[v]          = base + at * (sv - c0);
                    msg[NV + v]     = base + at * (sv - c1);
                    msg[2 * NV + v] = base + at * (sv - c2);
                }
                __syncthreads();
            }
        }

        // ---------- posterior + hard decision ----------
#pragma unroll
        for (int k = 0; k < VPT; k++) {
            int v = tid + k * TPB;
            float post = llrv[k] + (msg[v] + msg[NV + v] + msg[2 * NV + v]);
            size_t idx = (size_t)cw * NV + v;
            if (mode) {
                // out = [decoded_bits (as f32 0/1) | posterior], each [B,N]
                out_f[idx] = (post < 0.0f) ? 1.0f : 0.0f;
                out_f[(size_t)B * NV + idx] = post;
            } else {
                out_i[idx] = (post < 0.0f) ? 1 : 0;
            }
        }
        __syncthreads();   // protect msg before next codeword reuses it
    }
}

extern "C" void kernel_launch(void* const* d_in, const int* in_sizes, int n_in,
                              void* d_out, int out_size) {
    // metadata order: llr [B,N] f32, edge_v [E] i32, edge_c [E] i32 (structure
    // implicit: edge_c = i>>1), beta [T] f32, alpha [T] f32
    const float* llr    = (const float*)d_in[0];
    const int*   edge_v = (const int*)  d_in[1];
    const float* beta   = (const float*)d_in[3];
    const float* alpha  = (const float*)d_in[4];

    int B = in_sizes[0] / NV;
    int T = in_sizes[3];
    int mode = (out_size >= 2 * B * NV) ? 1 : 0;

    cudaFuncSetAttribute((const void*)bp_kernel,
                         cudaFuncAttributeMaxDynamicSharedMemorySize, SMEM_BYTES);
    bp_kernel<<<B, TPB, SMEM_BYTES>>>(llr, edge_v, beta, alpha,
                                      (float*)d_out, (int*)d_out, B, T, mode);
}